// round 12
// baseline (speedup 1.0000x reference)
#include <cuda_runtime.h>

// ---------------------------------------------------------------------------
// yolo_detect_target — one kernel; block tail = REDUX.SUM -> packed smem
// atomic election -> one packed global atomic {counter|fail|biased sum}.
// No second barrier, no leader loop, no dependent global reads on the
// common path. Rare paths (early conf break, row-0 fail -> global max) in
// the last block only, with a spin on g_first_fail for rigorous visibility.
// g_acc / sh_acc field layout (u64):
//   bits [ 0,40) : sum of (fx + BIAS), fx = round(sum * 2^20)
//   bits [40,50) : fail count
//   bits [50,60) : completion counter
// ---------------------------------------------------------------------------

#define CONF_T     0.25f
#define THREADS    256
#define NWARPS     (THREADS / 32)
#define ROWS_PB    68
#define CPR        20                    // float4 chunks per row (C=80)
#define CHUNKS     (ROWS_PB * CPR)       // 1360
#define ITERS      6                     // ceil(1360/256)
#define FXSCALE_F  1048576.0f            // 2^20
#define FXSCALE_D  1048576.0
#define TCLAMP     (1 << 25)             // per-thread fx clamp (warp sum fits i32)
#define WBIAS      (1ll << 31)           // per-warp bias in smem acc
#define BCLAMP     (1ll << 30)           // per-block fx clamp
#define BBIAS      (1ll << 31)           // per-block bias in global acc
#define FAIL_UNIT  (1ull << 40)
#define CNT_SHIFT  50
#define CNT_UNIT   (1ull << 50)
#define SUM_MASK   ((1ull << 40) - 1ull)
#define FAIL_MASK  0x3ffull
#define MAX_BLOCKS 340                   // 340*(BBIAS+BCLAMP) < 2^40

__device__ unsigned long long g_acc        = 0ull;
__device__ int                g_first_fail = 0x7fffffff;

__device__ __forceinline__ float warp_max(float m) {
    #pragma unroll
    for (int off = 16; off; off >>= 1)
        m = fmaxf(m, __shfl_xor_sync(0xffffffffu, m, off));
    return m;
}
__device__ __forceinline__ float warp_sum(float s) {
    #pragma unroll
    for (int off = 16; off; off >>= 1)
        s += __shfl_xor_sync(0xffffffffu, s, off);
    return s;
}

__device__ __forceinline__ float row_max(const float* __restrict__ post,
                                         int row, int C) {
    float m = -3.4e38f;
    if (C == 80) {
        const float4* p = (const float4*)(post + (size_t)row * 80);
        #pragma unroll
        for (int i = 0; i < 20; i++) {
            float4 v = __ldg(p + i);
            m = fmaxf(m, fmaxf(fmaxf(v.x, v.y), fmaxf(v.z, v.w)));
        }
    } else {
        const float* p = post + (size_t)row * (size_t)C;
        for (int c = 0; c < C; c++) m = fmaxf(m, __ldg(p + c));
    }
    return m;
}

__global__ __launch_bounds__(THREADS)
void k_fused(const float* __restrict__ post,
             const float* __restrict__ boxes,
             int num, int rows_pb, int C, long long total_elems,
             float* __restrict__ out)
{
    const int lane = threadIdx.x & 31;
    const int wid  = threadIdx.x >> 5;
    __shared__ float              cmax[ROWS_PB * (CPR + 1)];  // pad 21
    __shared__ unsigned long long sh_acc;
    __shared__ float              sh_red[NWARPS];
    __shared__ int                sh_mode;   // 0 done, 1 global max, 2 partial
    __shared__ int                sh_K;

    if (threadIdx.x == 0) { sh_acc = 0ull; sh_mode = 0; }

    const int r0 = blockIdx.x * rows_pb;
    int rows_here = num - r0;
    if (rows_here > rows_pb) rows_here = rows_pb;
    if (rows_here < 0) rows_here = 0;

    float val  = 0.0f;
    bool  fail = false;

    if (C == 80 && rows_pb == ROWS_PB) {
        const float4* p4 = (const float4*)post + (long long)r0 * CPR;
        float4 b = make_float4(0.f, 0.f, 0.f, 0.f);
        const bool has_row = (threadIdx.x < rows_here);
        if (has_row) b = __ldg((const float4*)boxes + (r0 + threadIdx.x));

        if (rows_here == ROWS_PB) {
            float4 v[ITERS];
            #pragma unroll
            for (int i = 0; i < ITERS; i++) {
                int lc = i * THREADS + threadIdx.x;
                v[i] = (lc < CHUNKS) ? __ldg(p4 + lc)
                                     : make_float4(0.f, 0.f, 0.f, 0.f);
            }
            #pragma unroll
            for (int i = 0; i < ITERS; i++) {
                int lc = i * THREADS + threadIdx.x;
                if (lc < CHUNKS) {
                    float m3 = fmaxf(fmaxf(v[i].x, v[i].y), fmaxf(v[i].z, v[i].w));
                    int r = lc / CPR;
                    int c = lc - r * CPR;
                    cmax[r * (CPR + 1) + c] = m3;
                }
            }
        } else {
            const int nchunks = rows_here * CPR;
            for (int lc = threadIdx.x; lc < nchunks; lc += THREADS) {
                float4 v = __ldg(p4 + lc);
                float m3 = fmaxf(fmaxf(v.x, v.y), fmaxf(v.z, v.w));
                int r = lc / CPR;
                int c = lc - r * CPR;
                cmax[r * (CPR + 1) + c] = m3;
            }
        }
        __syncthreads();   // orders cmax AND sh_acc/sh_mode init

        if (has_row) {
            const float* cm = &cmax[threadIdx.x * (CPR + 1)];
            float t0 = fmaxf(cm[0],  cm[1]),  t1 = fmaxf(cm[2],  cm[3]);
            float t2 = fmaxf(cm[4],  cm[5]),  t3 = fmaxf(cm[6],  cm[7]);
            float t4 = fmaxf(cm[8],  cm[9]),  t5 = fmaxf(cm[10], cm[11]);
            float t6 = fmaxf(cm[12], cm[13]), t7 = fmaxf(cm[14], cm[15]);
            float t8 = fmaxf(cm[16], cm[17]), t9 = fmaxf(cm[18], cm[19]);
            float u0 = fmaxf(t0, t1), u1 = fmaxf(t2, t3);
            float u2 = fmaxf(t4, t5), u3 = fmaxf(t6, t7);
            float u4 = fmaxf(t8, t9);
            float m  = fmaxf(fmaxf(fmaxf(u0, u1), fmaxf(u2, u3)), u4);
            val = m + ((b.x + b.y) + (b.z + b.w));
            if (!(m >= CONF_T)) {
                fail = true;
                atomicMin(&g_first_fail, r0 + threadIdx.x);
                __threadfence();
            }
        }
    } else {
        __syncthreads();   // orders sh_acc/sh_mode init
        for (int row = r0 + threadIdx.x; row < r0 + rows_here; row += THREADS) {
            float m = row_max(post, row, C);
            float4 b = __ldg((const float4*)boxes + row);
            val += m + ((b.x + b.y) + (b.z + b.w));
            if (!(m >= CONF_T)) {
                fail = true;
                atomicMin(&g_first_fail, row);
                __threadfence();
            }
        }
    }

    // ---- warp reduce (REDUX) + smem election + global atomic ---------------
    int fx = __float2int_rn(val * FXSCALE_F);
    if (fx >  TCLAMP) fx =  TCLAMP;
    if (fx < -TCLAMP) fx = -TCLAMP;
    int wfx = __reduce_add_sync(0xffffffffu, fx);
    unsigned wfail = __ballot_sync(0xffffffffu, fail);

    if (lane == 0) {
        unsigned long long wc = (unsigned long long)((long long)wfx + WBIAS)
                              + (wfail ? FAIL_UNIT : 0ull) + CNT_UNIT;
        unsigned long long old = atomicAdd(&sh_acc, wc);
        if ((old >> CNT_SHIFT) == (unsigned long long)(NWARPS - 1)) {
            // last warp of this block: block totals in-register
            unsigned long long bf = old + wc;
            long long bfx = (long long)(bf & SUM_MASK) - (long long)NWARPS * WBIAS;
            if (bfx >  BCLAMP) bfx =  BCLAMP;
            if (bfx < -BCLAMP) bfx = -BCLAMP;
            unsigned long long contrib =
                (unsigned long long)(bfx + BBIAS)
                + ((((bf >> 40) & FAIL_MASK) != 0ull) ? FAIL_UNIT : 0ull)
                + CNT_UNIT;

            unsigned long long gold;
            asm volatile("atom.add.release.gpu.global.u64 %0, [%1], %2;"
                         : "=l"(gold) : "l"(&g_acc), "l"(contrib) : "memory");

            if ((gold >> CNT_SHIFT) == (unsigned long long)(gridDim.x - 1)) {
                unsigned long long fin = gold + contrib;
                if (((fin >> 40) & FAIL_MASK) == 0ull) {
                    // common case: answer entirely in-register
                    long long tot = (long long)(fin & SUM_MASK)
                                  - (long long)gridDim.x * BBIAS;
                    out[0] = (float)((double)tot / FXSCALE_D);
                    *(volatile unsigned long long*)&g_acc = 0ull;
                } else {
                    asm volatile("fence.acquire.gpu;" ::: "memory");
                    int ff;
                    // eventual visibility of atomicMin guarantees termination
                    while ((ff = *(volatile int*)&g_first_fail) == 0x7fffffff) { }
                    int K = (ff < num) ? ff : num;
                    if (K == 0) sh_mode = 1;
                    else        { sh_mode = 2; sh_K = K; }
                }
            }
        }
    }
    __syncthreads();
    const int mode = sh_mode;
    if (mode == 0) return;

    // ================= rare paths (last block only) =========================
    if (mode == 1) {
        // row 0 failed -> loss = max over all of post
        float m = -3.4e38f;
        const long long n4 = total_elems >> 2;
        const float4* p4 = (const float4*)post;
        for (long long i = threadIdx.x; i < n4; i += THREADS) {
            float4 v = p4[i];
            m = fmaxf(m, fmaxf(fmaxf(v.x, v.y), fmaxf(v.z, v.w)));
        }
        for (long long i = (n4 << 2) + threadIdx.x; i < total_elems; i += THREADS)
            m = fmaxf(m, post[i]);
        m = warp_max(m);
        if (lane == 0) sh_red[wid] = m;
        __syncthreads();
        if (threadIdx.x == 0) {
            float r = sh_red[0];
            #pragma unroll
            for (int i = 1; i < NWARPS; i++) r = fmaxf(r, sh_red[i]);
            out[0] = r;
            *(volatile unsigned long long*)&g_acc = 0ull;
            *(volatile int*)&g_first_fail = 0x7fffffff;
        }
    } else {
        // early break at K (>=1) -> recompute sum over rows [0, K)
        const int K = sh_K;
        float s2 = 0.0f;
        for (int r = threadIdx.x; r < K; r += THREADS) {
            float m = row_max(post, r, C);
            float4 b = __ldg((const float4*)boxes + r);
            s2 += m + ((b.x + b.y) + (b.z + b.w));
        }
        s2 = warp_sum(s2);
        __syncthreads();
        if (lane == 0) sh_red[wid] = s2;
        __syncthreads();
        if (threadIdx.x == 0) {
            float t = 0.0f;
            #pragma unroll
            for (int i = 0; i < NWARPS; i++) t += sh_red[i];
            out[0] = t;
            *(volatile unsigned long long*)&g_acc = 0ull;
            *(volatile int*)&g_first_fail = 0x7fffffff;
        }
    }
}

extern "C" void kernel_launch(void* const* d_in, const int* in_sizes, int n_in,
                              void* d_out, int out_size)
{
    const float* post  = (const float*)d_in[0];   // [N, C] fp32
    const float* boxes = (const float*)d_in[1];   // [N, 4] fp32
    const long long total = (long long)in_sizes[0];
    const int N = in_sizes[1] / 4;
    const int C = (int)(total / N);

    int num = (int)((double)N * 0.02);
    if (num < 1) num = 1;
    if (num > N) num = N;

    int rows_pb, blocks;
    if (C == 80 && num <= ROWS_PB * MAX_BLOCKS) {
        rows_pb = ROWS_PB;                          // compile-time fast path
        blocks  = (num + rows_pb - 1) / rows_pb;    // 295 for num=20000
    } else {
        blocks  = (num + THREADS - 1) / THREADS;
        if (blocks > MAX_BLOCKS) blocks = MAX_BLOCKS;
        rows_pb = (num + blocks - 1) / blocks;
    }
    k_fused<<<blocks, THREADS>>>(post, boxes, num, rows_pb, C, total,
                                 (float*)d_out);
}